// round 17
// baseline (speedup 1.0000x reference)
#include <cuda_runtime.h>
#include <cuda_fp16.h>
#include <cstdint>

static constexpr int NB = 16, NN = 2048, DD = 64;
static constexpr int BM = 64, BN = 64, NKT = NN / BN, TB = 256;

// Pre-converted fp16 (hi only), SW128-swizzled. t: 0=Q,1=K,2=V
__device__ __align__(128) uint8_t g_conv[(size_t)3 * 16 * 16 * 16384];

// SMEM (76KB/CTA -> 2 CTAs/SM):
//   QH 8K @0
//   ST0=8192: 3-stage ring, stride STG3=16KB: {Kh 8K, Vh 8K}
//   SM_L row-sum scratch
//   SM_P: padded P stage, 64 rows x 288B (bank-shift 8 per row)
static constexpr int SM_QH = 0;
static constexpr int ST0 = 8192, STG3 = 16384;
static constexpr int SM_L = ST0 + 3 * STG3;       // 57344
static constexpr int SM_P = SM_L + 512;           // 57856
static constexpr int PSTR = 288;
static constexpr int SMEM_TOTAL = SM_P + 64 * PSTR;   // 76288

__device__ __forceinline__ uint32_t smem_u32(const void* p) {
    uint32_t a;
    asm("{ .reg .u64 t; cvta.to.shared.u64 t, %1; cvt.u32.u64 %0, t; }" : "=r"(a) : "l"(p));
    return a;
}
__device__ __forceinline__ uint32_t sw128(uint32_t bo) { return bo ^ ((bo >> 3) & 0x70); }
__device__ __forceinline__ float ex2f(float x) {
    float y; asm("ex2.approx.f32 %0, %1;" : "=f"(y) : "f"(x)); return y;
}
__device__ __forceinline__ uint32_t hpack(float a, float b) {
    __half2 h = __floats2half2_rn(a, b);
    return *reinterpret_cast<uint32_t*>(&h);
}

__device__ __forceinline__ void cpa16(uint32_t s, const void* g) {
    asm volatile("cp.async.cg.shared.global [%0], [%1], 16;" :: "r"(s), "l"(g));
}
#define CP_COMMIT() asm volatile("cp.async.commit_group;" ::: "memory")
#define CP_WAIT0()  asm volatile("cp.async.wait_group 0;" ::: "memory")
#define CP_WAIT1()  asm volatile("cp.async.wait_group 1;" ::: "memory")

__device__ __forceinline__ void gcopy(uint32_t sdst, const uint8_t* gsrc,
                                      int bytes, int tid) {
    for (int off = tid * 16; off < bytes; off += TB * 16)
        cpa16(sdst + off, gsrc + off);
}

#define LDSM4(r0,r1,r2,r3,ad) \
    asm volatile("ldmatrix.sync.aligned.m8n8.x4.shared.b16 {%0,%1,%2,%3}, [%4];" \
        : "=r"(r0), "=r"(r1), "=r"(r2), "=r"(r3) : "r"(ad))
#define LDSM4T(r0,r1,r2,r3,ad) \
    asm volatile("ldmatrix.sync.aligned.m8n8.x4.trans.shared.b16 {%0,%1,%2,%3}, [%4];" \
        : "=r"(r0), "=r"(r1), "=r"(r2), "=r"(r3) : "r"(ad))

__device__ __forceinline__ void mma16816(float* c, const uint32_t* a, const uint32_t* b) {
    asm volatile("mma.sync.aligned.m16n8k16.row.col.f32.f16.f16.f32 "
        "{%0,%1,%2,%3}, {%4,%5,%6,%7}, {%8,%9}, {%0,%1,%2,%3};"
        : "+f"(c[0]), "+f"(c[1]), "+f"(c[2]), "+f"(c[3])
        : "r"(a[0]), "r"(a[1]), "r"(a[2]), "r"(a[3]), "r"(b[0]), "r"(b[1]));
}

__device__ __forceinline__ void lda_frag(uint32_t* fr, uint32_t tile, int row0, int kbyte) {
    int lane = threadIdx.x & 31;
    int r = row0 + (lane & 7) + (lane & 8);
    int cb = kbyte + ((lane & 16) ? 16 : 0);
    LDSM4(fr[0], fr[1], fr[2], fr[3], tile + sw128((uint32_t)(r * 128 + cb)));
}
__device__ __forceinline__ void ldb_k(uint32_t* fr, uint32_t tile, int n0, int kbyte) {
    int lane = threadIdx.x & 31;
    int r = n0 + (lane & 7) + ((lane & 16) ? 8 : 0);
    int cb = kbyte + ((lane & 8) ? 16 : 0);
    LDSM4(fr[0], fr[1], fr[2], fr[3], tile + sw128((uint32_t)(r * 128 + cb)));
}
__device__ __forceinline__ void ldb_v(uint32_t* fr, uint32_t tile, int k0, int dbyte) {
    int lane = threadIdx.x & 31;
    int r = k0 + (lane & 7) + (lane & 8);
    int cb = dbyte + ((lane & 16) ? 16 : 0);
    LDSM4T(fr[0], fr[1], fr[2], fr[3], tile + sw128((uint32_t)(r * 128 + cb)));
}

// -------------------------------------------------- pre-convert fp32 -> fp16 (hi only)
__global__ void __launch_bounds__(256)
conv_kernel(const float* __restrict__ q, const float* __restrict__ k,
            const float* __restrict__ v)
{
    const int blk = blockIdx.x, b = blockIdx.y, t = blockIdx.z;
    const float* src = (t == 0 ? q : (t == 1 ? k : v)) + ((size_t)b * NN + blk * 128) * DD;
    uint8_t* dH = g_conv + (((size_t)t * 16 + b) * 16 + blk) * 16384;
    for (int e = threadIdx.x; e < 128 * 16; e += 256) {
        int row = e >> 4, c4 = (e & 15) << 2;
        float4 f = *(const float4*)(src + row * DD + c4);
        uint32_t bo = (uint32_t)(row * 128 + c4 * 2);
        *(uint32_t*)(dH + sw128(bo))     = hpack(f.x, f.y);
        *(uint32_t*)(dH + sw128(bo + 4)) = hpack(f.z, f.w);
    }
}

// -------------------------------------------------- main attention kernel
__global__ void __launch_bounds__(TB, 2)
attn_kernel(const float* __restrict__ scp, float* __restrict__ ctx,
            float* __restrict__ att)
{
    extern __shared__ char smem[];
    const uint32_t sb = smem_u32(smem);
    const int tid = threadIdx.x, lane = tid & 31, wid = tid >> 5;
    const int wr0 = (wid >> 1) * 16;       // warp's first q-row (0..48)
    const int nh = wid & 1;                // n-half (== k-half for PV)
    const int n0 = nh * 32;
    const int gr = lane >> 2, c2 = (lane & 3) * 2;
    const int b = blockIdx.y, q0 = blockIdx.x * BM;
    const float cexp = scp[0] * 1.4426950408889634f;

    const uint8_t* qsrc  = g_conv + (((size_t)0 * 16 + b) * 16) * 16384 + (size_t)blockIdx.x * 8192;
    const uint8_t* kbase = g_conv + (((size_t)1 * 16 + b) * 16) * 16384;
    const uint8_t* vbase = g_conv + (((size_t)2 * 16 + b) * 16) * 16384;

    // prologue: group0 = Q panel + Kh(0); group1 = Kh(1)
    gcopy(sb + SM_QH, qsrc, 8192, tid);
    gcopy(sb + ST0, kbase, 8192, tid);
    CP_COMMIT();
    gcopy(sb + ST0 + STG3, kbase + 8192, 8192, tid);
    CP_COMMIT();

    float rs0 = 0.f, rs1 = 0.f;
    uint32_t aQ[16];   // Q fragments, persistent across BOTH passes

    // ================= pass 1: row sums (Qh*Kh, fp16 exp) =================
    for (int kt = 0; kt < NKT; kt++) {
        if (kt + 1 < NKT) { CP_WAIT1(); } else { CP_WAIT0(); }
        __syncthreads();
        if (kt + 2 < NKT) {
            gcopy(sb + ST0 + (uint32_t)((kt + 2) % 3) * STG3,
                  kbase + (size_t)(kt + 2) * 8192, 8192, tid);
            CP_COMMIT();
        }
        if (kt == 0) {
            #pragma unroll
            for (int ks = 0; ks < 4; ks++)
                lda_frag(aQ + ks * 4, sb + SM_QH, wr0, ks * 32);
        }
        const uint32_t kst = sb + ST0 + (uint32_t)(kt % 3) * STG3;
        float sacc[16];
        #pragma unroll
        for (int i = 0; i < 16; i++) sacc[i] = 0.f;
        #pragma unroll
        for (int ks = 0; ks < 4; ks++) {
            #pragma unroll
            for (int nb2 = 0; nb2 < 2; nb2++) {
                uint32_t bH[4];
                ldb_k(bH, kst, n0 + nb2 * 16, ks * 32);
                float* c0 = sacc + nb2 * 8;
                mma16816(c0, aQ + ks*4, bH);  mma16816(c0 + 4, aQ + ks*4, bH + 2);
            }
        }
        #pragma unroll
        for (int nb = 0; nb < 4; nb++) {
            __half2 ha = __floats2half2_rn(sacc[nb*4+0] * cexp, sacc[nb*4+1] * cexp);
            __half2 hb = __floats2half2_rn(sacc[nb*4+2] * cexp, sacc[nb*4+3] * cexp);
            float2 ea = __half22float2(h2exp2(ha));
            float2 eb = __half22float2(h2exp2(hb));
            rs0 += ea.x + ea.y;
            rs1 += eb.x + eb.y;
        }
    }

    // ---- row-sum reduce across the two n-halves ----
    rs0 += __shfl_xor_sync(0xffffffff, rs0, 1);
    rs0 += __shfl_xor_sync(0xffffffff, rs0, 2);
    rs1 += __shfl_xor_sync(0xffffffff, rs1, 1);
    rs1 += __shfl_xor_sync(0xffffffff, rs1, 2);
    float* Ls = (float*)(smem + SM_L);
    __syncthreads();          // all pass-1 stage reads done
    if ((lane & 3) == 0) {
        Ls[nh * 64 + wr0 + gr]     = rs0;
        Ls[nh * 64 + wr0 + 8 + gr] = rs1;
    }
    __syncthreads();
    const float li0 = 1.0f / (Ls[wr0 + gr]     + Ls[64 + wr0 + gr]);
    const float li1 = 1.0f / (Ls[wr0 + 8 + gr] + Ls[64 + wr0 + 8 + gr]);

    float oacc[32];
    #pragma unroll
    for (int i = 0; i < 32; i++) oacc[i] = 0.f;

    // ================= pass 2: attention + O (3-stage ring) =================
    // stage layout: Kh @ +0, Vh @ +8192
    {
        uint32_t s0a = sb + ST0;
        gcopy(s0a,        kbase, 8192, tid);
        gcopy(s0a + 8192, vbase, 8192, tid);
        CP_COMMIT();
        uint32_t s1a = sb + ST0 + STG3;
        gcopy(s1a,        kbase + 8192, 8192, tid);
        gcopy(s1a + 8192, vbase + 8192, 8192, tid);
        CP_COMMIT();
    }

    // coalesced-writeout indices: warp owns rows 8*wid..8*wid+7
    const int wrow = (wid << 3) + (lane >> 4);   // +2j below
    const int wseg = lane & 15;

    for (int kt = 0; kt < NKT; kt++) {
        if (kt + 1 < NKT) { CP_WAIT1(); } else { CP_WAIT0(); }
        __syncthreads();   // A: stage kt ready, P(kt-1) fully consumed
        if (kt + 2 < NKT) {
            uint32_t sa = sb + ST0 + (uint32_t)((kt + 2) % 3) * STG3;
            gcopy(sa,        kbase + (size_t)(kt + 2) * 8192, 8192, tid);
            gcopy(sa + 8192, vbase + (size_t)(kt + 2) * 8192, 8192, tid);
            CP_COMMIT();
        }
        const uint32_t stg = sb + ST0 + (uint32_t)(kt % 3) * STG3;
        const uint32_t vst = stg + 8192;

        // QK: identical 1-product recompute (same aQ, same K bits as pass 1)
        float sacc[16];
        #pragma unroll
        for (int i = 0; i < 16; i++) sacc[i] = 0.f;
        #pragma unroll
        for (int ks = 0; ks < 4; ks++) {
            #pragma unroll
            for (int nb2 = 0; nb2 < 2; nb2++) {
                uint32_t bH[4];
                ldb_k(bH, stg, n0 + nb2 * 16, ks * 32);
                float* c0 = sacc + nb2 * 8;
                mma16816(c0, aQ + ks*4, bH);  mma16816(c0 + 4, aQ + ks*4, bH + 2);
            }
        }

        // epilogue: STS normalized P (padded) + pack e + PV, interleaved per ks2
        #pragma unroll
        for (int ks2 = 0; ks2 < 2; ks2++) {
            uint32_t ph[4];
            #pragma unroll
            for (int j = 0; j < 2; j++) {
                const int nb = 2 * ks2 + j;
                float e0 = ex2f(sacc[nb*4+0] * cexp);
                float e1 = ex2f(sacc[nb*4+1] * cexp);
                float e2 = ex2f(sacc[nb*4+2] * cexp);
                float e3 = ex2f(sacc[nb*4+3] * cexp);
                char* pp = smem + SM_P + (wr0 + gr) * PSTR + (n0 + nb * 8 + c2) * 4;
                *(float2*)(pp)            = make_float2(e0 * li0, e1 * li0);
                *(float2*)(pp + 8 * PSTR) = make_float2(e2 * li1, e3 * li1);
                ph[j*2 + 0] = hpack(e0, e1);
                ph[j*2 + 1] = hpack(e2, e3);
            }
            const int k0 = n0 + ks2 * 16;
            #pragma unroll
            for (int db2 = 0; db2 < 4; db2++) {
                uint32_t bH[4];
                ldb_v(bH, vst, k0, db2 * 32);
                float* c0 = oacc + db2 * 8;
                mma16816(c0, ph, bH);     mma16816(c0 + 4, ph, bH + 2);
            }
        }
        __syncthreads();   // B: P(kt) complete, stage kt consumed

        // coalesced att writeout: 2 full 256B rows per STG.128 instruction
        {
            float* abase = att + ((size_t)b * NN + q0) * NN + kt * BN + wseg * 4;
            #pragma unroll
            for (int j = 0; j < 4; j++) {
                const int row = wrow + 2 * j;
                float4 p4 = *(float4*)(smem + SM_P + row * PSTR + wseg * 16);
                *(float4*)(abase + (size_t)row * NN) = p4;
            }
        }
    }

    // ---- normalize O, reduce across nh warp-pairs, write context ----
    #pragma unroll
    for (int db2 = 0; db2 < 4; db2++) {
        oacc[db2*8+0] *= li0;  oacc[db2*8+1] *= li0;
        oacc[db2*8+2] *= li1;  oacc[db2*8+3] *= li1;
        oacc[db2*8+4] *= li0;  oacc[db2*8+5] *= li0;
        oacc[db2*8+6] *= li1;  oacc[db2*8+7] *= li1;
    }
    __syncthreads();   // ring + P areas reusable
    {
        char* red = smem + ST0 + (size_t)(wid >> 1) * 4096;  // 16 rows x 64 cols f32
        if (nh == 1) {
            #pragma unroll
            for (int db = 0; db < 8; db++) {
                const int q = (db >> 1) * 8 + (db & 1) * 4;
                *(float2*)(red + ((uint32_t)(gr)     * 64 + db * 8 + c2) * 4) =
                    make_float2(oacc[q+0], oacc[q+1]);
                *(float2*)(red + ((uint32_t)(gr + 8) * 64 + db * 8 + c2) * 4) =
                    make_float2(oacc[q+2], oacc[q+3]);
            }
        }
        __syncthreads();
        if (nh == 0) {
            float* crow0 = ctx + ((size_t)b * NN + q0 + wr0 + gr) * DD + c2;
            float* crow1 = crow0 + 8 * DD;
            #pragma unroll
            for (int db = 0; db < 8; db++) {
                const int q = (db >> 1) * 8 + (db & 1) * 4;
                float2 a0 = *(float2*)(red + ((uint32_t)(gr)     * 64 + db * 8 + c2) * 4);
                float2 a1 = *(float2*)(red + ((uint32_t)(gr + 8) * 64 + db * 8 + c2) * 4);
                *(float2*)(crow0 + db * 8) = make_float2(oacc[q+0] + a0.x, oacc[q+1] + a0.y);
                *(float2*)(crow1 + db * 8) = make_float2(oacc[q+2] + a1.x, oacc[q+3] + a1.y);
            }
        }
    }
}

extern "C" void kernel_launch(void* const* d_in, const int* in_sizes, int n_in,
                              void* d_out, int out_size) {
    const float* q  = (const float*)d_in[0];
    const float* k  = (const float*)d_in[1];
    const float* v  = (const float*)d_in[2];
    const float* sc = (const float*)d_in[3];
    float* ctx = (float*)d_out;                          // [16,2048,64]
    float* att = (float*)d_out + (size_t)NB * NN * DD;   // [16,2048,2048]

    conv_kernel<<<dim3(16, NB, 3), 256>>>(q, k, v);

    cudaFuncSetAttribute(attn_kernel, cudaFuncAttributeMaxDynamicSharedMemorySize, SMEM_TOTAL);
    dim3 grid(NN / BM, NB);
    attn_kernel<<<grid, TB, SMEM_TOTAL>>>(sc, ctx, att);
}